// round 9
// baseline (speedup 1.0000x reference)
#include <cuda_runtime.h>
#include <cstdint>
typedef uint32_t u32;
typedef unsigned long long u64;

#define XP 1288                       // channel pitch in words (≡8 mod 32, conflict-free)
#define BW_OFF (28 * XP)              // 36064 words: start of B quad table
#define SMEM_WORDS (BW_OFF + 10368)
#define SMEM_BYTES (SMEM_WORDS * 4)   // 185728 B

__device__ __forceinline__ u32 f2t(float f) {
    u32 r; asm("cvt.rna.tf32.f32 %0, %1;" : "=r"(r) : "f"(f)); return r;
}

__device__ __forceinline__ void mma8(float& d0, float& d1, float& d2, float& d3,
                                     u32 a0, u32 a1, u32 a2, u32 a3, u32 b0, u32 b1) {
    asm("mma.sync.aligned.m16n8k8.row.col.f32.tf32.tf32.f32 "
        "{%0,%1,%2,%3},{%4,%5,%6,%7},{%8,%9},{%0,%1,%2,%3};"
        : "+f"(d0), "+f"(d1), "+f"(d2), "+f"(d3)
        : "r"(a0), "r"(a1), "r"(a2), "r"(a3), "r"(b0), "r"(b1));
}

// out[b, n*32+cc, h, w] = sum_{c<16,kh,kw} x[b,(4cc-c)&127,(h-kh)&31,(w-kw)&31] * W[n,c,kh,kw]
// CTA = (g, b). Warp = one (h, m-tile) per pass, 4 passes. M-row r -> w = 2r / 2(r-8)+1,
// so each thread's A window is 10 contiguous words (5 LDS.64). B hoisted to regs per kh
// (9 LDS.128). K = 16-channel band per jc, 2 k8 steps; 81 taps accumulate in registers.
__global__ __launch_bounds__(512, 1)
void fconv_mma(const float* __restrict__ x, const float* __restrict__ w,
               float* __restrict__ out)
{
    extern __shared__ u32 sm[];
    u32* xs = sm;                 // [c<28][h<32][j<40], j = w + 8 (circular halo)
    u32* Bs = sm + BW_OFF;        // quads: [tap][n<8][tq<4][q<4], q = 2u+half
                                  //   value = W[n, 15-(8u+tq+4half), tap] (tf32)

    const int t = threadIdx.x, g = blockIdx.x, b = blockIdx.y;
    const int chb = (16 * g + 113) & 127;          // (16g - 15) mod 128
    const float* xb = x + (size_t)b * 131072;

    // ---- stage x as tf32, halo'd rows of 40 ----
    for (int i = t; i < 28 * 1280; i += 512) {
        int c = i / 1280, r = i % 1280, hh = r / 40, j = r % 40;
        xs[c * XP + hh * 40 + j] =
            f2t(xb[((chb + c) & 127) * 1024 + hh * 32 + ((j + 24) & 31)]);
    }
    // ---- stage B quads ----
    for (int i = t; i < 10368; i += 512) {
        int tap = i >> 7, r = i & 127;
        int n = r >> 4, tq = (r >> 2) & 3, q = r & 3;
        int u = q >> 1, half = q & 1;
        int k = 8 * u + tq + 4 * half;             // c = 15-k in 0..15
        Bs[i] = f2t(w[n * 1296 + (15 - k) * 81 + tap]);
    }
    __syncthreads();

    const int lane = t & 31, wid = t >> 5, gq = lane >> 2, tq = lane & 3;
    const uint4* Bq = (const uint4*)Bs;            // [tap*32 + gq*4 + tq]

    #pragma unroll 1
    for (int pass = 0; pass < 4; ++pass) {
        const int h = wid + 16 * (pass & 1);
        const int mt = pass >> 1;
        float acc[4][4];
        #pragma unroll
        for (int jc = 0; jc < 4; ++jc)
            #pragma unroll
            for (int q = 0; q < 4; ++q) acc[jc][q] = 0.f;

        #pragma unroll 1
        for (int kh = 0; kh < 9; ++kh) {
            const int row = (h - kh) & 31;
            const u32* xrow = xs + row * 40 + 2 * gq + 16 * mt;

            // hoist B for this kh: BB[kw] = (u0b0, u0b1, u1b0, u1b1)
            uint4 BB[9];
            #pragma unroll
            for (int kw = 0; kw < 9; ++kw)
                BB[kw] = Bq[(kh * 9 + kw) * 32 + gq * 4 + tq];

            // CH[buf][0..9] = x[chunk ch][row][w = 2gq-8+16mt + j], chunk c -> buf c%3
            u32 CH[3][10];
            #pragma unroll
            for (int ci = 0; ci < 2; ++ci) {
                const u32* p = xrow + (4 * ci + tq) * XP;
                #pragma unroll
                for (int q = 0; q < 5; ++q) {
                    uint2 v = *(const uint2*)(p + 2 * q);
                    CH[ci][2 * q] = v.x; CH[ci][2 * q + 1] = v.y;
                }
            }

            #pragma unroll
            for (int i = 0; i < 6; ++i) {
                if (i < 5) {   // prefetch chunk i+2 into buf (i+2)%3 (holds dead chunk i-1)
                    const u32* p = xrow + (4 * (i + 2) + tq) * XP;
                    #pragma unroll
                    for (int q = 0; q < 5; ++q) {
                        uint2 v = *(const uint2*)(p + 2 * q);
                        CH[(i + 2) % 3][2 * q] = v.x;
                        CH[(i + 2) % 3][2 * q + 1] = v.y;
                    }
                }
                const int lob = i % 3, hib = (i + 1) % 3;
                #pragma unroll
                for (int kw = 0; kw < 9; ++kw) {
                    // (jc = i, ks = 0) valid i<4 ; (jc = i-2, ks = 1) valid i>=2
                    if (i < 4)
                        mma8(acc[i][0], acc[i][1], acc[i][2], acc[i][3],
                             CH[lob][8 - kw], CH[lob][9 - kw],
                             CH[hib][8 - kw], CH[hib][9 - kw],
                             BB[kw].x, BB[kw].y);
                    if (i >= 2)
                        mma8(acc[i - 2][0], acc[i - 2][1], acc[i - 2][2], acc[i - 2][3],
                             CH[lob][8 - kw], CH[lob][9 - kw],
                             CH[hib][8 - kw], CH[hib][9 - kw],
                             BB[kw].z, BB[kw].w);
                }
            }
        }

        // ---- store: thread gq rows -> w = 2gq+16mt (+1); cols 2tq, 2tq+1 ----
        #pragma unroll
        for (int jc = 0; jc < 4; ++jc) {
            const int cc = 4 * g + jc;
            const int w0 = 2 * gq + 16 * mt;
            #pragma unroll
            for (int d = 0; d < 2; ++d) {
                const int ch = (2 * tq + d) * 32 + cc;
                float2 s = make_float2(acc[jc][d], acc[jc][2 + d]);
                *(float2*)(out + (size_t)b * 262144 + (size_t)ch * 1024
                           + h * 32 + w0) = s;
            }
        }
    }
}

extern "C" void kernel_launch(void* const* d_in, const int* in_sizes, int n_in,
                              void* d_out, int out_size)
{
    const float* x = (const float*)d_in[0];   // (32,128,32,32) f32
    const float* w = (const float*)d_in[1];   // (8,16,9,9) f32
    float* out = (float*)d_out;               // (32,256,32,32) f32

    cudaFuncSetAttribute(fconv_mma,
                         cudaFuncAttributeMaxDynamicSharedMemorySize, SMEM_BYTES);
    dim3 grid(8, 32);
    fconv_mma<<<grid, 512, SMEM_BYTES>>>(x, w, out);
}

// round 10
// speedup vs baseline: 1.6929x; 1.6929x over previous
#include <cuda_runtime.h>
#include <cuda_fp16.h>
#include <cstdint>
typedef uint32_t u32;

#define XPP 648                       // half2 words per cp plane (≡8 mod 32)
#define BW_OFF (14 * XPP)             // 9072
#define SMEM_WORDS (BW_OFF + 5184)
#define SMEM_BYTES (SMEM_WORDS * 4)   // 57024 B

__device__ __forceinline__ void mma16(float& d0, float& d1, float& d2, float& d3,
                                      u32 a0, u32 a1, u32 a2, u32 a3, u32 b0, u32 b1) {
    asm("mma.sync.aligned.m16n8k16.row.col.f32.f16.f16.f32 "
        "{%0,%1,%2,%3},{%4,%5,%6,%7},{%8,%9},{%0,%1,%2,%3};"
        : "+f"(d0), "+f"(d1), "+f"(d2), "+f"(d3)
        : "r"(a0), "r"(a1), "r"(a2), "r"(a3), "r"(b0), "r"(b1));
}

__device__ __forceinline__ u32 h2(float a, float b) {
    __half2 v = __floats2half2_rn(a, b);      // .x = a (low half)
    return *reinterpret_cast<u32*>(&v);
}

// out[b, n*32+cc, h, w] = sum_{c<16,kh,kw} x[b,(4cc-c)&127,(h-kh)&31,(w-kw)&31] * W[n,c,kh,kw]
// CTA = (g, h-quarter, b). Warp = one (h, m16 tile). M-row r -> w = 2r / 2(r-8)+1.
// K = 16-channel band per jc in ONE m16n8k16 fp16 mma; A k-pairs are half2 channel
// pairs; band for jc starts at channel 4jc -> pair index cp = 2jc + tq (+4 for k+8).
__global__ __launch_bounds__(512, 1)
void fconv_mma(const float* __restrict__ x, const float* __restrict__ w,
               float* __restrict__ out)
{
    extern __shared__ u32 sm[];
    u32* xs = sm;                 // [cp<14][r<16][j<40] half2(x[2cp], x[2cp+1])
    u32* Bs = sm + BW_OFF;        // [tap][gq(n)][tq][u] half2(W pair along k)

    const int t = threadIdx.x;
    const int g = blockIdx.x & 7, hq = blockIdx.x >> 3, b = blockIdx.y;
    const int chb = (16 * g + 113) & 127;          // (16g - 15) mod 128
    const float* xb = x + (size_t)b * 131072;

    // ---- stage x channel-pairs, rows 8hq-8 .. 8hq+7, halo'd cols of 40 ----
    for (int i = t; i < 8960; i += 512) {
        int cp = i / 640, r2 = i % 640, r = r2 / 40, j = r2 % 40;
        int h = (8 * hq - 8 + r) & 31, wc = (j + 24) & 31;
        float f0 = xb[((chb + 2 * cp)     & 127) * 1024 + h * 32 + wc];
        float f1 = xb[((chb + 2 * cp + 1) & 127) * 1024 + h * 32 + wc];
        xs[cp * XPP + r * 40 + j] = h2(f0, f1);
    }
    // ---- stage B: Bs[((tap*8+n)*4+tq)*2+u] = half2(W[n][15-(8u+2tq)], W[n][14-8u-2tq])[tap]
    for (int i = t; i < 5184; i += 512) {
        int u = i & 1, tq = (i >> 1) & 3, n = (i >> 3) & 7, tap = i >> 6;
        int c0 = 15 - (8 * u + 2 * tq);
        Bs[i] = h2(w[n * 1296 + c0 * 81 + tap], w[n * 1296 + (c0 - 1) * 81 + tap]);
    }
    __syncthreads();

    const int lane = t & 31, wid = t >> 5, gq = lane >> 2, tq = lane & 3;
    const int hloc = wid & 7, mt = wid >> 3;
    const int h = 8 * hq + hloc;

    float acc[4][4];
    #pragma unroll
    for (int jc = 0; jc < 4; ++jc)
        #pragma unroll
        for (int q = 0; q < 4; ++q) acc[jc][q] = 0.f;

    #pragma unroll 1
    for (int kh = 0; kh < 9; ++kh) {
        const int rl = hloc + 8 - kh;                 // staged row, 0..15
        const u32* xrow = xs + rl * 40 + 2 * gq + 16 * mt;

        // B for this kh: one LDS.64 per kw
        u32 BB0[9], BB1[9];
        #pragma unroll
        for (int kw = 0; kw < 9; ++kw) {
            uint2 v = *(const uint2*)(Bs + (((kh * 9 + kw) * 8 + gq) * 4 + tq) * 2);
            BB0[kw] = v.x; BB1[kw] = v.y;
        }
        // A windows: 6 channel-pair planes (cp = tq + 2d), 10 half2 each
        u32 CH[6][10];
        #pragma unroll
        for (int d = 0; d < 6; ++d) {
            const u32* p = xrow + (tq + 2 * d) * XPP;
            #pragma unroll
            for (int q = 0; q < 5; ++q) {
                uint2 v = *(const uint2*)(p + 2 * q);
                CH[d][2 * q] = v.x; CH[d][2 * q + 1] = v.y;
            }
        }
        #pragma unroll
        for (int kw = 0; kw < 9; ++kw)
            #pragma unroll
            for (int jc = 0; jc < 4; ++jc)
                mma16(acc[jc][0], acc[jc][1], acc[jc][2], acc[jc][3],
                      CH[jc][8 - kw], CH[jc][9 - kw],
                      CH[jc + 2][8 - kw], CH[jc + 2][9 - kw],
                      BB0[kw], BB1[kw]);
    }

    // ---- store: rows (gq, gq+8) -> w = (2gq, 2gq+1) + 16mt; cols 2tq,2tq+1 ----
    #pragma unroll
    for (int jc = 0; jc < 4; ++jc) {
        const int cc = 4 * g + jc;
        const int w0 = 2 * gq + 16 * mt;
        #pragma unroll
        for (int d = 0; d < 2; ++d) {
            const int ch = (2 * tq + d) * 32 + cc;
            float2 s = make_float2(acc[jc][d], acc[jc][2 + d]);
            *(float2*)(out + (size_t)b * 262144 + (size_t)ch * 1024
                       + h * 32 + w0) = s;
        }
    }
}

extern "C" void kernel_launch(void* const* d_in, const int* in_sizes, int n_in,
                              void* d_out, int out_size)
{
    const float* x = (const float*)d_in[0];   // (32,128,32,32) f32
    const float* w = (const float*)d_in[1];   // (8,16,9,9) f32
    float* out = (float*)d_out;               // (32,256,32,32) f32

    cudaFuncSetAttribute(fconv_mma,
                         cudaFuncAttributeMaxDynamicSharedMemorySize, SMEM_BYTES);
    dim3 grid(32, 32);                        // (g, hq) x b  -> 1024 CTAs
    fconv_mma<<<grid, 512, SMEM_BYTES>>>(x, w, out);
}